// round 10
// baseline (speedup 1.0000x reference)
#include <cuda_runtime.h>
#include <cstdint>

#define LL   50
#define DD   64
#define EE   128
#define UU   256     // hidden units total
#define UH   64      // hidden units per pass (4 passes)
#define NT   256     // 8 warps; 3 CTAs/SM
#define LT   12      // l's per tile-warp

#define FFMA2(acc, w, k) asm("fma.rn.f32x2 %0, %1, %2, %0;" : "+l"(acc) : "l"(w), "l"(k))
#define PACK2(dst, f)    asm("mov.b64 %0, {%1, %1};" : "=l"(dst) : "r"(__float_as_uint(f)))
#define UNPK2(lo, hi, s) do { unsigned _ulo, _uhi; \
    asm("mov.b64 {%0, %1}, %2;" : "=r"(_ulo), "=r"(_uhi) : "l"(s)); \
    lo = __uint_as_float(_ulo); hi = __uint_as_float(_uhi); } while (0)

// smem floats: sW2q 128*64 | sk 6400 | sq 128 | sAbh 64 | sAq 16*64 | sWout 256 | s_half[4][64] | s_acc 64
#define SMEM_FLOATS (128*UH + 6400 + 128 + 64 + 16*UH + 256 + 256 + 64)
#define SMEM_BYTES  (SMEM_FLOATS*4 + 64*4)

extern "C" __global__ void __launch_bounds__(NT, 3)
din_fused_kernel(const int*   __restrict__ qid_item,
                 const int*   __restrict__ qid_cate,
                 const int*   __restrict__ sid_item,
                 const int*   __restrict__ sid_cate,
                 const int*   __restrict__ mask,    // bool widened to 4B; nonzero == true
                 const float* __restrict__ emb_item,
                 const float* __restrict__ emb_cate,
                 const float* __restrict__ W_hide,
                 const float* __restrict__ b_hide,
                 const float* __restrict__ W_out,
                 const float* __restrict__ b_out,
                 float*       __restrict__ out)
{
    extern __shared__ float smem[];
    float* sW2q   = smem;                    // [128 d][64 u_local] (reused per pass)
    float* sk     = sW2q + 128*UH;           // [50][128]
    float* sq     = sk   + LL*EE;            // [128]
    float* sAbh   = sq   + 128;              // [64] (per pass)
    float* sAq    = sAbh + 64;               // [16][64] strip partials
    float* sWout  = sAq  + 16*UH;            // [256]
    float* s_half = sWout + UU;              // [4][64] per-pass partial scores
    float* s_acc  = s_half + 256;            // [64]
    int*   sactive= (int*)(s_acc + 64);      // [56]
    int*   scnt   = sactive + 56;            // [2]

    const int b    = blockIdx.x;
    const int tid  = threadIdx.x;
    const int warp = tid >> 5;
    const int lane = tid & 31;

    // ---------------- Phase 1: gathers + ballot compaction ------------------
    unsigned bal = 0; bool act = false;
    if (warp < 2) {
        const int l = (warp << 5) + lane;
        act = (l < LL) && (mask[(size_t)b*LL + l] != 0);
        bal = __ballot_sync(0xffffffffu, act);
        if (lane == 0) scnt[warp] = __popc(bal);
    }
    if (tid < EE) {
        const int qi = qid_item[b];
        const int qc = qid_cate[b];
        sq[tid] = (tid < DD) ? emb_item[(size_t)qi*DD + tid]
                             : emb_cate[(size_t)qc*DD + (tid - DD)];
    }
    sWout[tid] = W_out[tid];                  // NT == 256 == UU
    // K gather, float4: 50*32 float4 cells
    for (int idx = tid; idx < LL*32; idx += NT) {
        const int l  = idx >> 5;
        const int e4 = idx & 31;
        float4 v;
        if (e4 < 16) v = *(const float4*)(emb_item + (size_t)sid_item[(size_t)b*LL + l]*DD + (e4 << 2));
        else         v = *(const float4*)(emb_cate + (size_t)sid_cate[(size_t)b*LL + l]*DD + ((e4 - 16) << 2));
        *(float4*)(sk + (l << 7) + (e4 << 2)) = v;
    }
    __syncthreads();

    // compaction write (deterministic order via ballot prefix)
    if (warp < 2 && act) {
        const int off = (warp == 1) ? scnt[0] : 0;
        sactive[off + __popc(bal & ((1u << lane) - 1u))] = (warp << 5) + lane;
    }
    __syncthreads();

    const int nact  = scnt[0] + scnt[1];
    const int tiles = (nact + LT - 1) / LT;   // <= 5

    // ================= Four passes over u-quarters ===========================
    #pragma unroll 1
    for (int h = 0; h < 4; h++) {
        const int gub = h << 6;               // global u base of this quarter

        // ---- Phase 2: fold W2q = Wk + q*Wp for this quarter; Aq partials ----
        {
            const int u4    = (tid & 15) << 2;  // 4 consecutive local u (16 groups)
            const int strip = tid >> 4;         // 16 strips
            const int d0    = strip << 3;       // 8 d-rows per strip
            const int gu    = gub + u4;
            float4 aq = make_float4(0.f, 0.f, 0.f, 0.f);
            #pragma unroll
            for (int i = 0; i < 8; i++) {
                const int d = d0 + i;
                const float qd = sq[d];
                const float4 wk = *(const float4*)(W_hide + (size_t)(128 + d)*UU + gu);
                const float4 wp = *(const float4*)(W_hide + (size_t)(256 + d)*UU + gu);
                const float4 wq = *(const float4*)(W_hide + (size_t)d*UU + gu);
                float4 w2;
                w2.x = fmaf(qd, wp.x, wk.x);
                w2.y = fmaf(qd, wp.y, wk.y);
                w2.z = fmaf(qd, wp.z, wk.z);
                w2.w = fmaf(qd, wp.w, wk.w);
                *(float4*)(sW2q + (d << 6) + u4) = w2;
                aq.x = fmaf(qd, wq.x, aq.x);
                aq.y = fmaf(qd, wq.y, aq.y);
                aq.z = fmaf(qd, wq.z, aq.z);
                aq.w = fmaf(qd, wq.w, aq.w);
            }
            *(float4*)(sAq + strip*UH + u4) = aq;
        }
        __syncthreads();
        if (tid < UH) {
            float a = b_hide[gub + tid];
            #pragma unroll
            for (int s = 0; s < 16; s++) a += sAq[s*UH + tid];
            sAbh[tid] = a;
        }
        __syncthreads();

        // ---- Phase 3: mainloop (12 l's per warp, this u-quarter) -------------
        if (warp < tiles) {
            const int i0 = warp * LT;
            int nl = nact - i0; if (nl > LT) nl = LT;

            int koff[LT];
            #pragma unroll
            for (int t = 0; t < LT; t++)
                koff[t] = sactive[(t < nl) ? i0 + t : i0] << 7;

            const int up = lane << 1;          // 2 local u per lane (1 packed pair)
            const unsigned long long iA = *(const unsigned long long*)(sAbh + up);
            unsigned long long A[LT];
            #pragma unroll
            for (int t = 0; t < LT; t++) A[t] = iA;

            for (int d0 = 0; d0 < EE; d0 += 4) {
                // hoist weights for this 4-d block (reused across 3 l-groups)
                unsigned long long wA[4];
                #pragma unroll
                for (int dd = 0; dd < 4; dd++)
                    wA[dd] = *(const unsigned long long*)(sW2q + ((d0 + dd) << 6) + up);

                #pragma unroll
                for (int g = 0; g < 3; g++) {
                    float4 kv[4];
                    #pragma unroll
                    for (int t = 0; t < 4; t++)
                        kv[t] = *(const float4*)(sk + koff[g*4 + t] + d0);  // broadcast LDS.128
                    #pragma unroll
                    for (int dd = 0; dd < 4; dd++) {
                        #pragma unroll
                        for (int t = 0; t < 4; t++) {
                            unsigned long long kp;
                            PACK2(kp, ((const float*)&kv[t])[dd]);
                            FFMA2(A[g*4 + t], wA[dd], kp);
                        }
                    }
                }
            }

            // relu + W_out dot (partial over this quarter's 2 u's per lane)
            const float w0 = sWout[gub + up], w1 = sWout[gub + up + 1];
            float s[LT];
            #pragma unroll
            for (int t = 0; t < LT; t++) {
                float lo, hi;
                UNPK2(lo, hi, A[t]);
                s[t] = fmaxf(lo, 0.f)*w0 + fmaxf(hi, 0.f)*w1;
            }
            #pragma unroll
            for (int t = 0; t < LT; t++) {
                #pragma unroll
                for (int off = 16; off > 0; off >>= 1)
                    s[t] += __shfl_xor_sync(0xffffffffu, s[t], off);
            }
            if (lane == 0) {
                float* dst = s_half + (h << 6);
                #pragma unroll
                for (int t = 0; t < LT; t++)
                    if (t < nl) dst[i0 + t] = s[t];
            }
        }
        __syncthreads();   // sW2q/sAbh reuse next pass; s_half[h] now complete
    }

    // ---------------- Phase 4: combine passes + weighted sum + store ---------
    if (tid < 64 && tid < nact)
        s_acc[tid] = s_half[tid] + s_half[64 + tid] + s_half[128 + tid] + s_half[192 + tid];
    __syncthreads();

    if (tid < EE) {
        const float bo = b_out[0];
        float acc = 0.f;
        for (int i = 0; i < nact; i++)
            acc = fmaf(s_acc[i] + bo, sk[(sactive[i] << 7) + tid], acc);
        out[(size_t)b*EE + tid] = acc;
    }
}

extern "C" void kernel_launch(void* const* d_in, const int* in_sizes, int n_in,
                              void* d_out, int out_size)
{
    const int*   qid_item = (const int*)  d_in[0];
    const int*   qid_cate = (const int*)  d_in[1];
    const int*   sid_item = (const int*)  d_in[2];
    const int*   sid_cate = (const int*)  d_in[3];
    const int*   mask     = (const int*)  d_in[4];
    const float* emb_item = (const float*)d_in[5];
    const float* emb_cate = (const float*)d_in[6];
    const float* W_hide   = (const float*)d_in[7];
    const float* b_hide   = (const float*)d_in[8];
    const float* W_out    = (const float*)d_in[9];
    const float* b_out    = (const float*)d_in[10];
    float*       out      = (float*)      d_out;

    const int B = in_sizes[0];

    cudaFuncSetAttribute(din_fused_kernel,
                         cudaFuncAttributeMaxDynamicSharedMemorySize, SMEM_BYTES);

    din_fused_kernel<<<B, NT, SMEM_BYTES>>>(
        qid_item, qid_cate, sid_item, sid_cate, mask,
        emb_item, emb_cate, W_hide, b_hide, W_out, b_out, out);
}

// round 11
// speedup vs baseline: 1.2688x; 1.2688x over previous
#include <cuda_runtime.h>
#include <cstdint>

#define LL   50
#define DD   64
#define EE   128
#define UU   256     // hidden units total
#define UH   128     // hidden units per pass (2 passes)
#define NT   256     // 8 warps; 2 CTAs/SM

#define FFMA2(acc, w, k) asm("fma.rn.f32x2 %0, %1, %2, %0;" : "+l"(acc) : "l"(w), "l"(k))
#define PACK2(dst, f)    asm("mov.b64 %0, {%1, %1};" : "=l"(dst) : "r"(__float_as_uint(f)))
#define UNPK2(lo, hi, s) do { unsigned _ulo, _uhi; \
    asm("mov.b64 {%0, %1}, %2;" : "=r"(_ulo), "=r"(_uhi) : "l"(s)); \
    lo = __uint_as_float(_ulo); hi = __uint_as_float(_uhi); } while (0)

// smem floats: sW2q 128*128 | sk 6400 | sq 128 | sAbh 128 | sAq 8*128 | sWout 256 | s_half[2][64]
#define SMEM_FLOATS (128*UH + 6400 + 128 + 128 + 1024 + 256 + 128)
#define SMEM_BYTES  (SMEM_FLOATS*4 + 64*4)

extern "C" __global__ void __launch_bounds__(NT, 2)
din_fused_kernel(const int*   __restrict__ qid_item,
                 const int*   __restrict__ qid_cate,
                 const int*   __restrict__ sid_item,
                 const int*   __restrict__ sid_cate,
                 const int*   __restrict__ mask,    // bool widened to 4B; nonzero == true
                 const float* __restrict__ emb_item,
                 const float* __restrict__ emb_cate,
                 const float* __restrict__ W_hide,
                 const float* __restrict__ b_hide,
                 const float* __restrict__ W_out,
                 const float* __restrict__ b_out,
                 float*       __restrict__ out)
{
    extern __shared__ float smem[];
    float* sW2q   = smem;                    // [128 d][128 u_local] (reused per pass)
    float* sk     = sW2q + 128*UH;           // [50][128]
    float* sq     = sk   + LL*EE;            // [128]
    float* sAbh   = sq   + 128;              // [128] (per pass)
    float* sAq    = sAbh + 128;              // [8][128] strip partials
    float* sWout  = sAq  + 8*UH;             // [256]
    float* s_half = sWout + UU;              // [2][64] per-pass scores
    int*   sactive= (int*)(s_half + 128);    // [56]
    int*   scnt   = sactive + 56;            // [2]

    const int b    = blockIdx.x;
    const int tid  = threadIdx.x;
    const int warp = tid >> 5;
    const int lane = tid & 31;

    // ---------------- Phase 1: gathers + ballot compaction ------------------
    unsigned bal = 0; bool act = false;
    if (warp < 2) {
        const int l = (warp << 5) + lane;
        act = (l < LL) && (mask[(size_t)b*LL + l] != 0);
        bal = __ballot_sync(0xffffffffu, act);
        if (lane == 0) scnt[warp] = __popc(bal);
    }
    if (tid < EE) {
        const int qi = qid_item[b];
        const int qc = qid_cate[b];
        sq[tid] = (tid < DD) ? emb_item[(size_t)qi*DD + tid]
                             : emb_cate[(size_t)qc*DD + (tid - DD)];
    }
    sWout[tid] = W_out[tid];                  // NT == 256 == UU
    // K gather, float4: 50*32 float4 cells
    for (int idx = tid; idx < LL*32; idx += NT) {
        const int l  = idx >> 5;
        const int e4 = idx & 31;
        float4 v;
        if (e4 < 16) v = *(const float4*)(emb_item + (size_t)sid_item[(size_t)b*LL + l]*DD + (e4 << 2));
        else         v = *(const float4*)(emb_cate + (size_t)sid_cate[(size_t)b*LL + l]*DD + ((e4 - 16) << 2));
        *(float4*)(sk + (l << 7) + (e4 << 2)) = v;
    }
    __syncthreads();

    // compaction write (deterministic order via ballot prefix)
    if (warp < 2 && act) {
        const int off = (warp == 1) ? scnt[0] : 0;
        sactive[off + __popc(bal & ((1u << lane) - 1u))] = (warp << 5) + lane;
    }
    __syncthreads();

    const int nact = scnt[0] + scnt[1];

    // ================= Two passes over u-halves ==============================
    #pragma unroll 1
    for (int h = 0; h < 2; h++) {
        const int gub = h << 7;               // global u base of this half

        // ---- Phase 2: fold W2q = Wk + q*Wp for this half; Aq partials -------
        {
            const int u4 = lane << 2;         // 4 consecutive local u
            const int d0 = warp << 4;         // 16 d-rows per warp strip
            const int gu = gub + u4;
            float4 aq = make_float4(0.f, 0.f, 0.f, 0.f);
            #pragma unroll 4
            for (int i = 0; i < 16; i++) {
                const int d = d0 + i;
                const float qd = sq[d];
                const float4 wk = *(const float4*)(W_hide + (size_t)(128 + d)*UU + gu);
                const float4 wp = *(const float4*)(W_hide + (size_t)(256 + d)*UU + gu);
                const float4 wq = *(const float4*)(W_hide + (size_t)d*UU + gu);
                float4 w2;
                w2.x = fmaf(qd, wp.x, wk.x);
                w2.y = fmaf(qd, wp.y, wk.y);
                w2.z = fmaf(qd, wp.z, wk.z);
                w2.w = fmaf(qd, wp.w, wk.w);
                *(float4*)(sW2q + (d << 7) + u4) = w2;
                aq.x = fmaf(qd, wq.x, aq.x);
                aq.y = fmaf(qd, wq.y, aq.y);
                aq.z = fmaf(qd, wq.z, aq.z);
                aq.w = fmaf(qd, wq.w, aq.w);
            }
            *(float4*)(sAq + warp*UH + u4) = aq;
        }
        __syncthreads();
        if (tid < UH) {
            float a = b_hide[gub + tid];
            #pragma unroll
            for (int s = 0; s < 8; s++) a += sAq[s*UH + tid];
            sAbh[tid] = a;
        }
        __syncthreads();

        // ---- Phase 3: mainloop, 4-l tiles strided over warps -----------------
        // warp w handles l-indices [w*4, w*4+4), then [32+w*4, ...) (rare)
        for (int base = warp << 2; base < nact; base += 32) {
            int nv = nact - base; if (nv > 4) nv = 4;
            int koff[4];
            #pragma unroll
            for (int t = 0; t < 4; t++)
                koff[t] = sactive[(t < nv) ? base + t : base] << 7;

            const int up = lane << 2;          // 4 local u per lane (2 packed pairs)
            const unsigned long long* ab = (const unsigned long long*)(sAbh + up);
            const unsigned long long i00 = ab[0], i01 = ab[1];
            unsigned long long A[4][2];
            #pragma unroll
            for (int t = 0; t < 4; t++) { A[t][0] = i00; A[t][1] = i01; }

            for (int d0 = 0; d0 < EE; d0 += 4) {
                float4 kv[4];
                #pragma unroll
                for (int t = 0; t < 4; t++)
                    kv[t] = *(const float4*)(sk + koff[t] + d0);   // broadcast LDS.128

                #pragma unroll
                for (int dd = 0; dd < 4; dd++) {
                    const ulonglong2 wA = *(const ulonglong2*)(sW2q + ((d0 + dd) << 7) + up);
                    #pragma unroll
                    for (int t = 0; t < 4; t++) {
                        unsigned long long kp;
                        PACK2(kp, ((const float*)&kv[t])[dd]);
                        FFMA2(A[t][0], wA.x, kp);
                        FFMA2(A[t][1], wA.y, kp);
                    }
                }
            }

            // relu + W_out dot (partial over this half's 4 u's per lane)
            const float w0 = sWout[gub+up+0], w1 = sWout[gub+up+1];
            const float w2_= sWout[gub+up+2], w3 = sWout[gub+up+3];
            float s[4];
            #pragma unroll
            for (int t = 0; t < 4; t++) {
                float lo, hi, acc;
                UNPK2(lo, hi, A[t][0]); acc  = fmaxf(lo,0.f)*w0 + fmaxf(hi,0.f)*w1;
                UNPK2(lo, hi, A[t][1]); acc += fmaxf(lo,0.f)*w2_+ fmaxf(hi,0.f)*w3;
                s[t] = acc;
            }
            #pragma unroll
            for (int t = 0; t < 4; t++) {
                #pragma unroll
                for (int off = 16; off > 0; off >>= 1)
                    s[t] += __shfl_xor_sync(0xffffffffu, s[t], off);
            }
            if (lane == 0) {
                float* dst = s_half + (h << 6);
                #pragma unroll
                for (int t = 0; t < 4; t++)
                    if (t < nv) dst[base + t] = s[t];
            }
        }
        __syncthreads();   // sW2q/sAbh reused next pass; s_half[h] complete
    }

    // ---------------- Phase 4: combine passes + weighted sum + store ---------
    if (tid < EE) {
        const float bo = b_out[0];
        float acc = 0.f;
        for (int i = 0; i < nact; i++)
            acc = fmaf(s_half[i] + s_half[64 + i] + bo, sk[(sactive[i] << 7) + tid], acc);
        out[(size_t)b*EE + tid] = acc;
    }
}

extern "C" void kernel_launch(void* const* d_in, const int* in_sizes, int n_in,
                              void* d_out, int out_size)
{
    const int*   qid_item = (const int*)  d_in[0];
    const int*   qid_cate = (const int*)  d_in[1];
    const int*   sid_item = (const int*)  d_in[2];
    const int*   sid_cate = (const int*)  d_in[3];
    const int*   mask     = (const int*)  d_in[4];
    const float* emb_item = (const float*)d_in[5];
    const float* emb_cate = (const float*)d_in[6];
    const float* W_hide   = (const float*)d_in[7];
    const float* b_hide   = (const float*)d_in[8];
    const float* W_out    = (const float*)d_in[9];
    const float* b_out    = (const float*)d_in[10];
    float*       out      = (float*)      d_out;

    const int B = in_sizes[0];

    cudaFuncSetAttribute(din_fused_kernel,
                         cudaFuncAttributeMaxDynamicSharedMemorySize, SMEM_BYTES);

    din_fused_kernel<<<B, NT, SMEM_BYTES>>>(
        qid_item, qid_cate, sid_item, sid_cate, mask,
        emb_item, emb_cate, W_hide, b_hide, W_out, b_out, out);
}